// round 16
// baseline (speedup 1.0000x reference)
#include <cuda_runtime.h>
#include <cuda_fp16.h>
#include <math.h>
#include <stdint.h>

// Problem constants (fixed by the dataset)
#define TT 5
#define FIN 10
#define HID 16
#define MAXN 100000
#define MAXE 3200000
#define CAP 96            // fixed CSR slice capacity per node (divisible by 3 and 4)
#define XSTRIDE 64        // xT row stride in halves -> 128B aligned rows
#define XREAL  50
#define XREAL2 25         // half2 elements per xT row
#define F8STRIDE 128      // fp8 feature row stride in BYTES (80 data + pad)
#define FSTRIDE 80        // P row stride in halves (fp16)
#define K8 16.0f          // fp8 storage scale

// ---------------- device scratch (static: no allocation allowed) ----------------
// g_cursor: zero-based degree counters. Zero at load (.bss); reset to zero by the
// last reader (kprop8<0>) so every graph replay sees the same starting state.
// Feature arrays sized MAXN+1: row index n is the all-zero dummy row used by the
// triple-gather padding (never written).
__device__ int    g_cursor[MAXN];
__device__ float  g_dis[MAXN];
__device__ __align__(16) int           g_csrc[(size_t)MAXN * CAP];
__device__ __align__(16) __half        g_xT[(size_t)(MAXN + 1) * XSTRIDE];
__device__ __align__(16) unsigned char g_h1[(size_t)(MAXN + 1) * F8STRIDE];
__device__ __align__(16) unsigned char g_feats[(size_t)(MAXN + 1) * F8STRIDE];
__device__ __align__(16) __half        g_P[(size_t)(MAXN + 1) * FSTRIDE];

__device__ __forceinline__ __half2 bits_h2u(unsigned b) {
    return *reinterpret_cast<__half2*>(&b);
}
__device__ __forceinline__ float fast_tanh(float x) {
    float r;
    asm("tanh.approx.f32 %0, %1;" : "=f"(r) : "f"(x));
    return r;
}
__device__ __forceinline__ float fast_sig(float x) {
    return fmaf(0.5f, fast_tanh(0.5f * x), 0.5f);
}
// packed fp32x2 helpers (Blackwell FFMA2 — PTX-only)
__device__ __forceinline__ unsigned long long pack2(float lo, float hi) {
    unsigned long long r;
    asm("mov.b64 %0, {%1, %2};" : "=l"(r) : "f"(lo), "f"(hi));
    return r;
}
__device__ __forceinline__ void unpack2(float& lo, float& hi, unsigned long long v) {
    asm("mov.b64 {%0, %1}, %2;" : "=f"(lo), "=f"(hi) : "l"(v));
}
__device__ __forceinline__ unsigned long long fma2(unsigned long long a,
                                                   unsigned long long b,
                                                   unsigned long long c) {
    unsigned long long d;
    asm("fma.rn.f32x2 %0, %1, %2, %3;" : "=l"(d) : "l"(a), "l"(b), "l"(c));
    return d;
}
// fp8 e4m3 pack/unpack
__device__ __forceinline__ unsigned pack_e4m3x4(float a, float b, float c, float d) {
    unsigned short lo, hi;
    asm("cvt.rn.satfinite.e4m3x2.f32 %0, %1, %2;" : "=h"(lo) : "f"(b), "f"(a));
    asm("cvt.rn.satfinite.e4m3x2.f32 %0, %1, %2;" : "=h"(hi) : "f"(d), "f"(c));
    return (unsigned)lo | ((unsigned)hi << 16);
}
__device__ __forceinline__ void unpack_e4m3x4(unsigned q, __half2& p01, __half2& p23) {
    unsigned a, b;
    asm("{\n\t"
        ".reg .b16 lo, hi;\n\t"
        "mov.b32 {lo, hi}, %2;\n\t"
        "cvt.rn.f16x2.e4m3x2 %0, lo;\n\t"
        "cvt.rn.f16x2.e4m3x2 %1, hi;\n\t"
        "}" : "=r"(a), "=r"(b) : "r"(q));
    p01 = bits_h2u(a);
    p23 = bits_h2u(b);
}

// ---------------- stage 0: edge fill (zero-based cursors, single atomic pass) ----
__global__ void kfill(const int* __restrict__ src, const int* __restrict__ dst,
                      int* cursor, int* csrc, int e) {
    int i = blockIdx.x * blockDim.x + threadIdx.x;
    int j = i * 8;
    if (j + 8 <= e) {
        int4 s0 = __ldg((const int4*)(src + j));
        int4 s1 = __ldg((const int4*)(src + j + 4));
        int4 d0 = __ldg((const int4*)(dst + j));
        int4 d1 = __ldg((const int4*)(dst + j + 4));
        int p;
        p = atomicAdd(&cursor[d0.x], 1); if (p < CAP) csrc[d0.x * CAP + p] = s0.x;
        p = atomicAdd(&cursor[d0.y], 1); if (p < CAP) csrc[d0.y * CAP + p] = s0.y;
        p = atomicAdd(&cursor[d0.z], 1); if (p < CAP) csrc[d0.z * CAP + p] = s0.z;
        p = atomicAdd(&cursor[d0.w], 1); if (p < CAP) csrc[d0.w * CAP + p] = s0.w;
        p = atomicAdd(&cursor[d1.x], 1); if (p < CAP) csrc[d1.x * CAP + p] = s1.x;
        p = atomicAdd(&cursor[d1.y], 1); if (p < CAP) csrc[d1.y * CAP + p] = s1.y;
        p = atomicAdd(&cursor[d1.z], 1); if (p < CAP) csrc[d1.z * CAP + p] = s1.z;
        p = atomicAdd(&cursor[d1.w], 1); if (p < CAP) csrc[d1.w * CAP + p] = s1.w;
    } else {
        for (; j < e; j++) {
            int d = __ldg(dst + j);
            int p = atomicAdd(&cursor[d], 1);
            if (p < CAP) csrc[d * CAP + p] = __ldg(src + j);
        }
    }
}

// ---------------- stage 1: x transpose (pre-scaled) + dis + slice pad-to-3 ------
__global__ void ktransd(const float* __restrict__ x, __half* __restrict__ xT,
                        const int* __restrict__ cursor, float* __restrict__ dis,
                        int* __restrict__ csrc, int n) {
    int i = blockIdx.x * blockDim.x + threadIdx.x;
    if (i >= n * XREAL2) return;
    int node = i / XREAL2;
    int c2 = i - node * XREAL2;
    int deg = __ldg(cursor + node);
    if (deg > CAP) deg = CAP;
    float dd = rsqrtf((float)deg + 1.0f);
    if (c2 == 0) {
        dis[node] = dd;
        int r = deg % 3;                       // pad slice to multiple of 3 with
        if (r) {                               // the dummy (all-zero) row index n
            int endc = node * CAP + deg;
            csrc[endc] = n;
            if (r == 1) csrc[endc + 1] = n;
        }
    }
    int c = 2 * c2;
    int t = c / FIN;
    int f = c - t * FIN;
    float2 v = __ldg((const float2*)(x + ((size_t)t * n + node) * FIN + f));
    __half2 h = __floats2half2_rn(dd * v.x, dd * v.y);
    ((unsigned*)xT)[(size_t)node * (XSTRIDE / 2) + c2] =
        *reinterpret_cast<unsigned*>(&h);
}

// ---------------- stage 2: dual-row fp16 gather-sum -> fp8 transformed output ----
__global__ __launch_bounds__(256, 8) void kprop_x(const __half* __restrict__ in,
                                                  unsigned char* __restrict__ out,
                                                  const int* __restrict__ cursor,
                                                  const int* __restrict__ csrc,
                                                  const float* __restrict__ dis,
                                                  const float* __restrict__ Wm,
                                                  const float* __restrict__ bm, int n) {
    __shared__ float sAgg[8][52];
    __shared__ float sW[FIN * 16];
    __shared__ float sB[16];
    for (int i = threadIdx.x; i < FIN * 16; i += blockDim.x) sW[i] = Wm[i];
    if (threadIdx.x < 16) sB[threadIdx.x] = bm[threadIdx.x];
    __syncthreads();

    int wwid = threadIdx.x >> 5;
    int node = (blockIdx.x << 3) + wwid;
    if (node >= n) return;
    int lane = threadIdx.x & 31;
    bool grp = lane >= 16;
    int lh = lane & 15;
    int ll = (lh < 13) ? lh : 12;
    const unsigned FULL = 0xffffffffu;

    __half2 zero2 = __float2half2_rn(0.f);
    __half2 a0x = zero2, a0y = zero2, a1x = zero2, a1y = zero2;

    int j = node * CAP;
    int deg = __ldg(cursor + node);
    if (deg > CAP) deg = CAP;
    int end = j + deg;

    for (; j + 4 <= end; j += 4) {
        int4 e4 = __ldg((const int4*)(csrc + j));
        int sA = grp ? e4.y : e4.x;
        int sB2 = grp ? e4.w : e4.z;
        uint2 q0 = __ldg((const uint2*)(in + (size_t)sA * XSTRIDE) + ll);
        uint2 q1 = __ldg((const uint2*)(in + (size_t)sB2 * XSTRIDE) + ll);
        a0x = __hadd2(a0x, bits_h2u(q0.x));
        a0y = __hadd2(a0y, bits_h2u(q0.y));
        a1x = __hadd2(a1x, bits_h2u(q1.x));
        a1y = __hadd2(a1y, bits_h2u(q1.y));
    }
    if (j + 2 <= end) {
        int sA = csrc[j + (grp ? 1 : 0)];
        uint2 q = __ldg((const uint2*)(in + (size_t)sA * XSTRIDE) + ll);
        a0x = __hadd2(a0x, bits_h2u(q.x));
        a0y = __hadd2(a0y, bits_h2u(q.y));
        j += 2;
    }
    if (j < end) {
        int s = csrc[j];
        uint2 q = __ldg((const uint2*)(in + (size_t)s * XSTRIDE) + ll);
        if (!grp) {
            a0x = __hadd2(a0x, bits_h2u(q.x));
            a0y = __hadd2(a0y, bits_h2u(q.y));
        }
    }

    float2 c0 = __half22float2(a0x);
    float2 c1 = __half22float2(a1x);
    float f0 = c0.x + c1.x;
    float f1 = c0.y + c1.y;
    c0 = __half22float2(a0y);
    c1 = __half22float2(a1y);
    float f2 = c0.x + c1.x;
    float f3 = c0.y + c1.y;
    f0 += __shfl_down_sync(FULL, f0, 16);
    f1 += __shfl_down_sync(FULL, f1, 16);
    f2 += __shfl_down_sync(FULL, f2, 16);
    f3 += __shfl_down_sync(FULL, f3, 16);

    float dd = __ldg(dis + node);
    uint2 sq = __ldg((const uint2*)(in + (size_t)node * XSTRIDE) + ll);
    float2 s01 = __half22float2(bits_h2u(sq.x));
    float2 s23 = __half22float2(bits_h2u(sq.y));
    f0 = dd * (f0 + s01.x);
    f1 = dd * (f1 + s01.y);
    f2 = dd * (f2 + s23.x);
    f3 = dd * (f3 + s23.y);

    if (lane < 13) {
        float4 fv = make_float4(f0, f1, f2, f3);
        *(float4*)&sAgg[wwid][lane * 4] = fv;
    }
    __syncwarp();
    if (lane < 20) {
        float ks = K8 * dd;
        int c = lane * 4;
        int t = c >> 4;
        int h = c & 15;
        float o0 = sB[h], o1 = sB[h + 1], o2 = sB[h + 2], o3 = sB[h + 3];
#pragma unroll
        for (int f = 0; f < FIN; f++) {
            float a = sAgg[wwid][t * FIN + f];
            o0 = fmaf(a, sW[f * 16 + h],     o0);
            o1 = fmaf(a, sW[f * 16 + h + 1], o1);
            o2 = fmaf(a, sW[f * 16 + h + 2], o2);
            o3 = fmaf(a, sW[f * 16 + h + 3], o3);
        }
        unsigned pk = pack_e4m3x4(ks * fmaxf(o0, 0.f), ks * fmaxf(o1, 0.f),
                                  ks * fmaxf(o2, 0.f), ks * fmaxf(o3, 0.f));
        ((unsigned*)(out + (size_t)node * F8STRIDE))[lane] = pk;
    }
}

// ---------------- stages 3/4: TRIPLE-row fp8 gather-sum --------------------------
// MODE 0 additionally resets cursor[node] to 0 (last reader) for the next replay.
template <int MODE>
__global__ __launch_bounds__(256, 8) void kprop8(const unsigned char* __restrict__ in,
                                                 void* __restrict__ outv,
                                                 int* __restrict__ cursor,
                                                 const int* __restrict__ csrc,
                                                 const float* __restrict__ dis,
                                                 const float* __restrict__ Wm,
                                                 const float* __restrict__ bm, int n) {
    __shared__ float sAgg[MODE ? 8 : 1][MODE ? 80 : 4];
    __shared__ float sW[MODE ? HID * 16 : 1];
    __shared__ float sB[MODE ? 16 : 1];
    if (MODE) {
        for (int i = threadIdx.x; i < HID * 16; i += blockDim.x) sW[i] = Wm[i];
        if (threadIdx.x < 16) sB[threadIdx.x] = bm[threadIdx.x];
        __syncthreads();
    }
    int wwid = threadIdx.x >> 5;
    int node = (blockIdx.x << 3) + wwid;
    if (node >= n) return;
    int lane = threadIdx.x & 31;
    int g = lane / 10; if (g > 2) g = 2;
    int lh = lane - g * 10; if (lh > 9) lh = 9;
    const unsigned FULL = 0xffffffffu;

    __half2 zero2 = __float2half2_rn(0.f);
    __half2 a0 = zero2, a1 = zero2, a2 = zero2, a3 = zero2;

    int base = node * CAP;
    int deg = __ldg(cursor + node);
    if (deg > CAP) deg = CAP;
    if (MODE == 0 && lane == 31) cursor[node] = 0;   // reset for next replay
    int end3 = base + ((deg + 2) / 3) * 3;           // padded region is valid

    int j = base;
    for (; j + 6 <= end3; j += 6) {
        int s0 = __ldg(csrc + j + g);
        int s1 = __ldg(csrc + j + 3 + g);
        uint2 q0 = __ldg((const uint2*)(in + (size_t)s0 * F8STRIDE) + lh);
        uint2 q1 = __ldg((const uint2*)(in + (size_t)s1 * F8STRIDE) + lh);
        __half2 pa, pb;
        unpack_e4m3x4(q0.x, pa, pb); a0 = __hadd2(a0, pa); a1 = __hadd2(a1, pb);
        unpack_e4m3x4(q0.y, pa, pb); a2 = __hadd2(a2, pa); a3 = __hadd2(a3, pb);
        unpack_e4m3x4(q1.x, pa, pb); a0 = __hadd2(a0, pa); a1 = __hadd2(a1, pb);
        unpack_e4m3x4(q1.y, pa, pb); a2 = __hadd2(a2, pa); a3 = __hadd2(a3, pb);
    }
    if (j < end3) {
        int s0 = __ldg(csrc + j + g);
        uint2 q0 = __ldg((const uint2*)(in + (size_t)s0 * F8STRIDE) + lh);
        __half2 pa, pb;
        unpack_e4m3x4(q0.x, pa, pb); a0 = __hadd2(a0, pa); a1 = __hadd2(a1, pb);
        unpack_e4m3x4(q0.y, pa, pb); a2 = __hadd2(a2, pa); a3 = __hadd2(a3, pb);
    }

    float v[8];
    float2 t2;
    t2 = __half22float2(a0); v[0] = t2.x; v[1] = t2.y;
    t2 = __half22float2(a1); v[2] = t2.x; v[3] = t2.y;
    t2 = __half22float2(a2); v[4] = t2.x; v[5] = t2.y;
    t2 = __half22float2(a3); v[6] = t2.x; v[7] = t2.y;
#pragma unroll
    for (int k = 0; k < 8; k++) {
        float b1v = __shfl_sync(FULL, v[k], lh + 10);
        float b2v = __shfl_sync(FULL, v[k], lh + 20);
        v[k] += b1v + b2v;
    }

    float dd = __ldg(dis + node);
    float sc = dd * (1.0f / K8);
    uint2 sq = __ldg((const uint2*)(in + (size_t)node * F8STRIDE) + lh);
    __half2 sa, sb;
    unpack_e4m3x4(sq.x, sa, sb);
    float2 s01 = __half22float2(sa), s23 = __half22float2(sb);
    v[0] = sc * (v[0] + s01.x); v[1] = sc * (v[1] + s01.y);
    v[2] = sc * (v[2] + s23.x); v[3] = sc * (v[3] + s23.y);
    unpack_e4m3x4(sq.y, sa, sb);
    s01 = __half22float2(sa); s23 = __half22float2(sb);
    v[4] = sc * (v[4] + s01.x); v[5] = sc * (v[5] + s01.y);
    v[6] = sc * (v[6] + s23.x); v[7] = sc * (v[7] + s23.y);

    if (!MODE) {
        if (lane < 10) {
            __half2 p0 = __floats2half2_rn(v[0], v[1]);
            __half2 p1 = __floats2half2_rn(v[2], v[3]);
            __half2 p2 = __floats2half2_rn(v[4], v[5]);
            __half2 p3 = __floats2half2_rn(v[6], v[7]);
            uint4 pk;
            pk.x = *reinterpret_cast<unsigned*>(&p0);
            pk.y = *reinterpret_cast<unsigned*>(&p1);
            pk.z = *reinterpret_cast<unsigned*>(&p2);
            pk.w = *reinterpret_cast<unsigned*>(&p3);
            *((uint4*)((__half*)outv + (size_t)node * FSTRIDE) + lh) = pk;
        }
        return;
    }

    if (lane < 10) {
        *(float4*)&sAgg[wwid][lh * 8]     = make_float4(v[0], v[1], v[2], v[3]);
        *(float4*)&sAgg[wwid][lh * 8 + 4] = make_float4(v[4], v[5], v[6], v[7]);
    }
    __syncwarp();
    if (lane < 20) {
        float ks = K8 * dd;
        int c = lane * 4;
        int t = c >> 4;
        int h = c & 15;
        float o0 = sB[h], o1 = sB[h + 1], o2 = sB[h + 2], o3 = sB[h + 3];
#pragma unroll
        for (int f = 0; f < HID; f++) {
            float a = sAgg[wwid][t * HID + f];
            o0 = fmaf(a, sW[f * 16 + h],     o0);
            o1 = fmaf(a, sW[f * 16 + h + 1], o1);
            o2 = fmaf(a, sW[f * 16 + h + 2], o2);
            o3 = fmaf(a, sW[f * 16 + h + 3], o3);
        }
        unsigned pk = pack_e4m3x4(ks * fmaxf(o0, 0.f), ks * fmaxf(o1, 0.f),
                                  ks * fmaxf(o2, 0.f), ks * fmaxf(o3, 0.f));
        ((unsigned*)((unsigned char*)outv + (size_t)node * F8STRIDE))[lane] = pk;
    }
}

// ---------------- GRU (FFMA2, inline gate-fold) + attention + FC + log_softmax --
#define GRU_NPB 96
__global__ __launch_bounds__(GRU_NPB) void kgru(const __half* __restrict__ P,
                                                const float* __restrict__ Wz,
                                                const float* __restrict__ bz,
                                                const float* __restrict__ Wr,
                                                const float* __restrict__ br,
                                                const float* __restrict__ Wh,
                                                const float* __restrict__ bh,
                                                const float* __restrict__ Lz,
                                                const float* __restrict__ lz,
                                                const float* __restrict__ Lr,
                                                const float* __restrict__ lr,
                                                const float* __restrict__ Lh,
                                                const float* __restrict__ lh_,
                                                const float* __restrict__ att,
                                                const float* __restrict__ fcW,
                                                const float* __restrict__ fcb,
                                                float* __restrict__ out, int n) {
    __shared__ unsigned long long sM2z[128], sM2r[128], sM2h[128];
    __shared__ unsigned long long sL2z[128], sL2r[128], sL2h[128];
    __shared__ unsigned long long sB2z[8], sB2r[8], sB2h[8];
    __shared__ unsigned sPh[GRU_NPB * 41];
    __shared__ float sfcW[32], sfcb[2], sprob[TT];

    int tid = threadIdx.x;
    // inline fold: M* = W* @ L*[0:16] (pairs), L2* = L*[16:32] (pairs)
    for (int i = tid; i < 128; i += GRU_NPB) {
        int k = i >> 3, j = i & 7;
        int h0 = 2 * j;
        float mz0 = 0.f, mz1 = 0.f, mr0 = 0.f, mr1 = 0.f, mh0 = 0.f, mh1 = 0.f;
#pragma unroll
        for (int l = 0; l < 16; l++) {
            float wzk = __ldg(&Wz[k * 16 + l]);
            float wrk = __ldg(&Wr[k * 16 + l]);
            float whk = __ldg(&Wh[k * 16 + l]);
            mz0 = fmaf(wzk, __ldg(&Lz[l * 16 + h0]),     mz0);
            mz1 = fmaf(wzk, __ldg(&Lz[l * 16 + h0 + 1]), mz1);
            mr0 = fmaf(wrk, __ldg(&Lr[l * 16 + h0]),     mr0);
            mr1 = fmaf(wrk, __ldg(&Lr[l * 16 + h0 + 1]), mr1);
            mh0 = fmaf(whk, __ldg(&Lh[l * 16 + h0]),     mh0);
            mh1 = fmaf(whk, __ldg(&Lh[l * 16 + h0 + 1]), mh1);
        }
        sM2z[i] = pack2(mz0, mz1);
        sM2r[i] = pack2(mr0, mr1);
        sM2h[i] = pack2(mh0, mh1);
        int gi = k * 16 + h0;
        sL2z[i] = pack2(__ldg(&Lz[256 + gi]), __ldg(&Lz[256 + gi + 1]));
        sL2r[i] = pack2(__ldg(&Lr[256 + gi]), __ldg(&Lr[256 + gi + 1]));
        sL2h[i] = pack2(__ldg(&Lh[256 + gi]), __ldg(&Lh[256 + gi + 1]));
    }
    if (tid < 8) {
        int h0 = 2 * tid;
        float bz0 = __ldg(&lz[h0]), bz1 = __ldg(&lz[h0 + 1]);
        float br0 = __ldg(&lr[h0]), br1 = __ldg(&lr[h0 + 1]);
        float bh0 = __ldg(&lh_[h0]), bh1 = __ldg(&lh_[h0 + 1]);
#pragma unroll
        for (int l = 0; l < 16; l++) {
            bz0 = fmaf(__ldg(&bz[l]), __ldg(&Lz[l * 16 + h0]),     bz0);
            bz1 = fmaf(__ldg(&bz[l]), __ldg(&Lz[l * 16 + h0 + 1]), bz1);
            br0 = fmaf(__ldg(&br[l]), __ldg(&Lr[l * 16 + h0]),     br0);
            br1 = fmaf(__ldg(&br[l]), __ldg(&Lr[l * 16 + h0 + 1]), br1);
            bh0 = fmaf(__ldg(&bh[l]), __ldg(&Lh[l * 16 + h0]),     bh0);
            bh1 = fmaf(__ldg(&bh[l]), __ldg(&Lh[l * 16 + h0 + 1]), bh1);
        }
        sB2z[tid] = pack2(bz0, bz1);
        sB2r[tid] = pack2(br0, br1);
        sB2h[tid] = pack2(bh0, bh1);
    }
    if (tid < 32) sfcW[tid] = fcW[tid];
    if (tid < 2)  sfcb[tid] = fcb[tid];
    if (tid == 0) {
        float m = att[0];
        for (int t = 1; t < TT; t++) m = fmaxf(m, att[t]);
        float ex[TT]; float s = 0.f;
        for (int t = 0; t < TT; t++) { ex[t] = expf(att[t] - m); s += ex[t]; }
        for (int t = 0; t < TT; t++) sprob[t] = ex[t] / s;
    }
    int base = blockIdx.x * GRU_NPB;
    for (int i = tid; i < GRU_NPB * (FSTRIDE / 2); i += GRU_NPB) {
        int nd = i / (FSTRIDE / 2), c2 = i - nd * (FSTRIDE / 2);
        int g = base + nd;
        unsigned u = 0;
        if (g < n) u = __ldg((const unsigned*)(P + (size_t)g * FSTRIDE) + c2);
        sPh[nd * 41 + c2] = u;
    }
    __syncthreads();

    int node = base + tid;
    if (node >= n) return;
    const unsigned* myPh = &sPh[tid * 41];

    float H[16], Hacc[16];
#pragma unroll
    for (int h = 0; h < 16; h++) { H[h] = 0.f; Hacc[h] = 0.f; }

#pragma unroll 1
    for (int t = 0; t < TT; t++) {
        unsigned long long pk2[16], hk2[16];
#pragma unroll
        for (int k2 = 0; k2 < 8; k2++) {
            float2 pf = __half22float2(bits_h2u(myPh[t * 8 + k2]));
            pk2[2 * k2]     = pack2(pf.x, pf.x);
            pk2[2 * k2 + 1] = pack2(pf.y, pf.y);
        }
#pragma unroll
        for (int k = 0; k < 16; k++) hk2[k] = pack2(H[k], H[k]);

        unsigned long long acc[8];
        float a[16];
#pragma unroll
        for (int j = 0; j < 8; j++) acc[j] = sB2z[j];
#pragma unroll
        for (int k = 0; k < 16; k++) {
#pragma unroll
            for (int j = 0; j < 8; j++) {
                acc[j] = fma2(pk2[k], sM2z[k * 8 + j], acc[j]);
                acc[j] = fma2(hk2[k], sL2z[k * 8 + j], acc[j]);
            }
        }
        float Zg[16];
#pragma unroll
        for (int j = 0; j < 8; j++) unpack2(a[2 * j], a[2 * j + 1], acc[j]);
#pragma unroll
        for (int h = 0; h < 16; h++) Zg[h] = fast_sig(a[h]);

#pragma unroll
        for (int j = 0; j < 8; j++) acc[j] = sB2r[j];
#pragma unroll
        for (int k = 0; k < 16; k++) {
#pragma unroll
            for (int j = 0; j < 8; j++) {
                acc[j] = fma2(pk2[k], sM2r[k * 8 + j], acc[j]);
                acc[j] = fma2(hk2[k], sL2r[k * 8 + j], acc[j]);
            }
        }
        float Rg[16];
#pragma unroll
        for (int j = 0; j < 8; j++) unpack2(a[2 * j], a[2 * j + 1], acc[j]);
#pragma unroll
        for (int h = 0; h < 16; h++) Rg[h] = fast_sig(a[h]);

#pragma unroll
        for (int k = 0; k < 16; k++) {
            float hr = H[k] * Rg[k];
            hk2[k] = pack2(hr, hr);
        }
#pragma unroll
        for (int j = 0; j < 8; j++) acc[j] = sB2h[j];
#pragma unroll
        for (int k = 0; k < 16; k++) {
#pragma unroll
            for (int j = 0; j < 8; j++) {
                acc[j] = fma2(pk2[k], sM2h[k * 8 + j], acc[j]);
                acc[j] = fma2(hk2[k], sL2h[k * 8 + j], acc[j]);
            }
        }
#pragma unroll
        for (int j = 0; j < 8; j++) unpack2(a[2 * j], a[2 * j + 1], acc[j]);
#pragma unroll
        for (int h = 0; h < 16; h++) {
            float ht = fast_tanh(a[h]);
            H[h] = Zg[h] * H[h] + (1.f - Zg[h]) * ht;
            Hacc[h] = fmaf(sprob[t], H[h], Hacc[h]);
        }
    }

    float l0 = sfcb[0], l1 = sfcb[1];
#pragma unroll
    for (int h = 0; h < 16; h++) {
        l0 = fmaf(Hacc[h], sfcW[h * 2 + 0], l0);
        l1 = fmaf(Hacc[h], sfcW[h * 2 + 1], l1);
    }
    float m = fmaxf(l0, l1);
    float lse = m + logf(expf(l0 - m) + expf(l1 - m));
    out[(size_t)node * 2 + 0] = l0 - lse;
    out[(size_t)node * 2 + 1] = l1 - lse;
}

// ---------------- launch ----------------
extern "C" void kernel_launch(void* const* d_in, const int* in_sizes, int n_in,
                              void* d_out, int out_size) {
    const float* x   = (const float*)d_in[0];
    const int*   src = (const int*)d_in[1];
    const int*   dst = (const int*)d_in[2];
    const float* W1  = (const float*)d_in[3];
    const float* b1  = (const float*)d_in[4];
    const float* W2  = (const float*)d_in[5];
    const float* b2  = (const float*)d_in[6];
    const float* Wz  = (const float*)d_in[7];
    const float* bz  = (const float*)d_in[8];
    const float* Wr  = (const float*)d_in[9];
    const float* br  = (const float*)d_in[10];
    const float* Wh  = (const float*)d_in[11];
    const float* bh  = (const float*)d_in[12];
    const float* Lz  = (const float*)d_in[13];
    const float* lz  = (const float*)d_in[14];
    const float* Lr  = (const float*)d_in[15];
    const float* lr  = (const float*)d_in[16];
    const float* Lh  = (const float*)d_in[17];
    const float* lh  = (const float*)d_in[18];
    const float* att = (const float*)d_in[19];
    const float* fcW = (const float*)d_in[20];
    const float* fcb = (const float*)d_in[21];

    int n = in_sizes[0] / (TT * FIN);
    int e = in_sizes[1];

    void* p;
    cudaGetSymbolAddress(&p, g_cursor);  int*           cursor = (int*)p;
    cudaGetSymbolAddress(&p, g_dis);     float*         dis    = (float*)p;
    cudaGetSymbolAddress(&p, g_csrc);    int*           csrc   = (int*)p;
    cudaGetSymbolAddress(&p, g_xT);      __half*        xT     = (__half*)p;
    cudaGetSymbolAddress(&p, g_h1);      unsigned char* h1     = (unsigned char*)p;
    cudaGetSymbolAddress(&p, g_feats);   unsigned char* feats  = (unsigned char*)p;
    cudaGetSymbolAddress(&p, g_P);       __half*        P      = (__half*)p;

    int e8 = (e + 7) / 8;
    int prop_blocks = (n + 7) / 8;

    // 0: single-pass edge fill (zero-based cursors; no init kernel needed)
    kfill<<<(e8 + 255) / 256, 256>>>(src, dst, cursor, csrc, e);
    // 1: x transpose (pre-scaled) + dis + slice pad-to-3
    ktransd<<<(n * XREAL2 + 255) / 256, 256>>>(x, xT, cursor, dis, csrc, n);
    // 2: h1(fp8) = K8*dis*relu((S x) @ W1 + b1)   [dual-row gather]
    kprop_x<<<prop_blocks, 256>>>(xT, h1, cursor, csrc, dis, W1, b1, n);
    // 3: feats(fp8) = K8*dis*relu((S h1) @ W2 + b2)   [triple-row]  <-- profiled
    kprop8<1><<<prop_blocks, 256>>>(h1, feats, cursor, csrc, dis, W2, b2, n);
    // 4: P(fp16) = S feats [triple-row] + cursor reset for next replay
    kprop8<0><<<prop_blocks, 256>>>(feats, P, cursor, csrc, dis, W2, b2, n);
    // 5: GRU (FFMA2, inline gate-fold) + attention + FC + log_softmax
    kgru<<<(n + GRU_NPB - 1) / GRU_NPB, GRU_NPB>>>(P, Wz, bz, Wr, br, Wh, bh,
                                                   Lz, lz, Lr, lr, Lh, lh,
                                                   att, fcW, fcb, (float*)d_out, n);
}

// round 17
// speedup vs baseline: 1.0022x; 1.0022x over previous
#include <cuda_runtime.h>
#include <cuda_fp16.h>
#include <math.h>
#include <stdint.h>

// Problem constants (fixed by the dataset)
#define TT 5
#define FIN 10
#define HID 16
#define MAXN 100000
#define MAXE 3200000
#define CAP 96            // fixed CSR slice capacity per node (divisible by 3 and 4)
#define XSTRIDE 64        // xT row stride in halves -> 128B aligned rows
#define XREAL  50
#define XREAL2 25         // half2 elements per xT row
#define F8STRIDE 128      // fp8 feature row stride in BYTES (80 data + pad)
#define FSTRIDE 80        // P row stride in halves (fp16)
#define K8 16.0f          // fp8 storage scale

// ---------------- device scratch (static: no allocation allowed) ----------------
// g_cursor: zero-based degree counters. Zero at load (.bss); reset to zero by the
// last reader (kprop8<0>) so every graph replay sees identical starting state.
// Feature arrays sized MAXN+1: row index n is the all-zero dummy row used by the
// triple-gather padding (never written).
__device__ int    g_cursor[MAXN];
__device__ float  g_dis[MAXN];
__device__ __align__(16) int           g_csrc[(size_t)MAXN * CAP];
__device__ __align__(16) __half        g_xT[(size_t)(MAXN + 1) * XSTRIDE];
__device__ __align__(16) unsigned char g_h1[(size_t)(MAXN + 1) * F8STRIDE];
__device__ __align__(16) unsigned char g_feats[(size_t)(MAXN + 1) * F8STRIDE];
__device__ __align__(16) __half        g_P[(size_t)(MAXN + 1) * FSTRIDE];
__device__ float  g_Mz[256], g_Mr[256], g_Mh[256];
__device__ float  g_Bz[16],  g_Br[16],  g_Bh[16];

__device__ __forceinline__ __half2 bits_h2u(unsigned b) {
    return *reinterpret_cast<__half2*>(&b);
}
__device__ __forceinline__ float fast_tanh(float x) {
    float r;
    asm("tanh.approx.f32 %0, %1;" : "=f"(r) : "f"(x));
    return r;
}
__device__ __forceinline__ float fast_sig(float x) {
    return fmaf(0.5f, fast_tanh(0.5f * x), 0.5f);
}
// packed fp32x2 helpers (Blackwell FFMA2 — PTX-only)
__device__ __forceinline__ unsigned long long pack2(float lo, float hi) {
    unsigned long long r;
    asm("mov.b64 %0, {%1, %2};" : "=l"(r) : "f"(lo), "f"(hi));
    return r;
}
__device__ __forceinline__ void unpack2(float& lo, float& hi, unsigned long long v) {
    asm("mov.b64 {%0, %1}, %2;" : "=f"(lo), "=f"(hi) : "l"(v));
}
__device__ __forceinline__ unsigned long long fma2(unsigned long long a,
                                                   unsigned long long b,
                                                   unsigned long long c) {
    unsigned long long d;
    asm("fma.rn.f32x2 %0, %1, %2, %3;" : "=l"(d) : "l"(a), "l"(b), "l"(c));
    return d;
}
// fp8 e4m3 pack/unpack
__device__ __forceinline__ unsigned pack_e4m3x4(float a, float b, float c, float d) {
    unsigned short lo, hi;
    asm("cvt.rn.satfinite.e4m3x2.f32 %0, %1, %2;" : "=h"(lo) : "f"(b), "f"(a));
    asm("cvt.rn.satfinite.e4m3x2.f32 %0, %1, %2;" : "=h"(hi) : "f"(d), "f"(c));
    return (unsigned)lo | ((unsigned)hi << 16);
}
__device__ __forceinline__ void unpack_e4m3x4(unsigned q, __half2& p01, __half2& p23) {
    unsigned a, b;
    asm("{\n\t"
        ".reg .b16 lo, hi;\n\t"
        "mov.b32 {lo, hi}, %2;\n\t"
        "cvt.rn.f16x2.e4m3x2 %0, lo;\n\t"
        "cvt.rn.f16x2.e4m3x2 %1, hi;\n\t"
        "}" : "=r"(a), "=r"(b) : "r"(q));
    p01 = bits_h2u(a);
    p23 = bits_h2u(b);
}

// ---------------- fold gate matmuls (separate 1-block kernel — round-15 proven) --
__global__ void kprepG(const float* Wz, const float* bz, const float* Wr, const float* br,
                       const float* Wh, const float* bh,
                       const float* Lz, const float* lz, const float* Lr, const float* lr,
                       const float* Lh, const float* lh) {
    int tid = threadIdx.x;  // 256
    int k = tid >> 4, h = tid & 15;
    float mz = 0.f, mr = 0.f, mh = 0.f;
#pragma unroll
    for (int j = 0; j < 16; j++) {
        mz = fmaf(Wz[k * 16 + j], Lz[j * 16 + h], mz);
        mr = fmaf(Wr[k * 16 + j], Lr[j * 16 + h], mr);
        mh = fmaf(Wh[k * 16 + j], Lh[j * 16 + h], mh);
    }
    g_Mz[tid] = mz; g_Mr[tid] = mr; g_Mh[tid] = mh;
    if (tid < 16) {
        float az = lz[tid], ar = lr[tid], ah = lh[tid];
#pragma unroll
        for (int j = 0; j < 16; j++) {
            az = fmaf(bz[j], Lz[j * 16 + tid], az);
            ar = fmaf(br[j], Lr[j * 16 + tid], ar);
            ah = fmaf(bh[j], Lh[j * 16 + tid], ah);
        }
        g_Bz[tid] = az; g_Br[tid] = ar; g_Bh[tid] = ah;
    }
}

// ---------------- stage 1: edge fill (zero-based cursors, single atomic pass) ----
__global__ void kfill(const int* __restrict__ src, const int* __restrict__ dst,
                      int* cursor, int* csrc, int e) {
    int i = blockIdx.x * blockDim.x + threadIdx.x;
    int j = i * 8;
    if (j + 8 <= e) {
        int4 s0 = __ldg((const int4*)(src + j));
        int4 s1 = __ldg((const int4*)(src + j + 4));
        int4 d0 = __ldg((const int4*)(dst + j));
        int4 d1 = __ldg((const int4*)(dst + j + 4));
        int p;
        p = atomicAdd(&cursor[d0.x], 1); if (p < CAP) csrc[d0.x * CAP + p] = s0.x;
        p = atomicAdd(&cursor[d0.y], 1); if (p < CAP) csrc[d0.y * CAP + p] = s0.y;
        p = atomicAdd(&cursor[d0.z], 1); if (p < CAP) csrc[d0.z * CAP + p] = s0.z;
        p = atomicAdd(&cursor[d0.w], 1); if (p < CAP) csrc[d0.w * CAP + p] = s0.w;
        p = atomicAdd(&cursor[d1.x], 1); if (p < CAP) csrc[d1.x * CAP + p] = s1.x;
        p = atomicAdd(&cursor[d1.y], 1); if (p < CAP) csrc[d1.y * CAP + p] = s1.y;
        p = atomicAdd(&cursor[d1.z], 1); if (p < CAP) csrc[d1.z * CAP + p] = s1.z;
        p = atomicAdd(&cursor[d1.w], 1); if (p < CAP) csrc[d1.w * CAP + p] = s1.w;
    } else {
        for (; j < e; j++) {
            int d = __ldg(dst + j);
            int p = atomicAdd(&cursor[d], 1);
            if (p < CAP) csrc[d * CAP + p] = __ldg(src + j);
        }
    }
}

// ---------------- stage 2: x transpose (pre-scaled) + dis + slice pad-to-3 ------
__global__ void ktransd(const float* __restrict__ x, __half* __restrict__ xT,
                        const int* __restrict__ cursor, float* __restrict__ dis,
                        int* __restrict__ csrc, int n) {
    int i = blockIdx.x * blockDim.x + threadIdx.x;
    if (i >= n * XREAL2) return;
    int node = i / XREAL2;
    int c2 = i - node * XREAL2;
    int deg = __ldg(cursor + node);
    if (deg > CAP) deg = CAP;
    float dd = rsqrtf((float)deg + 1.0f);
    if (c2 == 0) {
        dis[node] = dd;
        int r = deg % 3;                       // pad slice to multiple of 3 with
        if (r) {                               // the dummy (all-zero) row index n
            int endc = node * CAP + deg;
            csrc[endc] = n;
            if (r == 1) csrc[endc + 1] = n;
        }
    }
    int c = 2 * c2;
    int t = c / FIN;
    int f = c - t * FIN;
    float2 v = __ldg((const float2*)(x + ((size_t)t * n + node) * FIN + f));
    __half2 h = __floats2half2_rn(dd * v.x, dd * v.y);
    ((unsigned*)xT)[(size_t)node * (XSTRIDE / 2) + c2] =
        *reinterpret_cast<unsigned*>(&h);
}

// ---------------- stage 3: dual-row fp16 gather-sum -> fp8 transformed output ----
__global__ __launch_bounds__(256, 8) void kprop_x(const __half* __restrict__ in,
                                                  unsigned char* __restrict__ out,
                                                  const int* __restrict__ cursor,
                                                  const int* __restrict__ csrc,
                                                  const float* __restrict__ dis,
                                                  const float* __restrict__ Wm,
                                                  const float* __restrict__ bm, int n) {
    __shared__ float sAgg[8][52];
    __shared__ float sW[FIN * 16];
    __shared__ float sB[16];
    for (int i = threadIdx.x; i < FIN * 16; i += blockDim.x) sW[i] = Wm[i];
    if (threadIdx.x < 16) sB[threadIdx.x] = bm[threadIdx.x];
    __syncthreads();

    int wwid = threadIdx.x >> 5;
    int node = (blockIdx.x << 3) + wwid;
    if (node >= n) return;
    int lane = threadIdx.x & 31;
    bool grp = lane >= 16;
    int lh = lane & 15;
    int ll = (lh < 13) ? lh : 12;
    const unsigned FULL = 0xffffffffu;

    __half2 zero2 = __float2half2_rn(0.f);
    __half2 a0x = zero2, a0y = zero2, a1x = zero2, a1y = zero2;

    int j = node * CAP;
    int deg = __ldg(cursor + node);
    if (deg > CAP) deg = CAP;
    int end = j + deg;

    for (; j + 4 <= end; j += 4) {
        int4 e4 = __ldg((const int4*)(csrc + j));
        int sA = grp ? e4.y : e4.x;
        int sB2 = grp ? e4.w : e4.z;
        uint2 q0 = __ldg((const uint2*)(in + (size_t)sA * XSTRIDE) + ll);
        uint2 q1 = __ldg((const uint2*)(in + (size_t)sB2 * XSTRIDE) + ll);
        a0x = __hadd2(a0x, bits_h2u(q0.x));
        a0y = __hadd2(a0y, bits_h2u(q0.y));
        a1x = __hadd2(a1x, bits_h2u(q1.x));
        a1y = __hadd2(a1y, bits_h2u(q1.y));
    }
    if (j + 2 <= end) {
        int sA = csrc[j + (grp ? 1 : 0)];
        uint2 q = __ldg((const uint2*)(in + (size_t)sA * XSTRIDE) + ll);
        a0x = __hadd2(a0x, bits_h2u(q.x));
        a0y = __hadd2(a0y, bits_h2u(q.y));
        j += 2;
    }
    if (j < end) {
        int s = csrc[j];
        uint2 q = __ldg((const uint2*)(in + (size_t)s * XSTRIDE) + ll);
        if (!grp) {
            a0x = __hadd2(a0x, bits_h2u(q.x));
            a0y = __hadd2(a0y, bits_h2u(q.y));
        }
    }

    float2 c0 = __half22float2(a0x);
    float2 c1 = __half22float2(a1x);
    float f0 = c0.x + c1.x;
    float f1 = c0.y + c1.y;
    c0 = __half22float2(a0y);
    c1 = __half22float2(a1y);
    float f2 = c0.x + c1.x;
    float f3 = c0.y + c1.y;
    f0 += __shfl_down_sync(FULL, f0, 16);
    f1 += __shfl_down_sync(FULL, f1, 16);
    f2 += __shfl_down_sync(FULL, f2, 16);
    f3 += __shfl_down_sync(FULL, f3, 16);

    float dd = __ldg(dis + node);
    uint2 sq = __ldg((const uint2*)(in + (size_t)node * XSTRIDE) + ll);
    float2 s01 = __half22float2(bits_h2u(sq.x));
    float2 s23 = __half22float2(bits_h2u(sq.y));
    f0 = dd * (f0 + s01.x);
    f1 = dd * (f1 + s01.y);
    f2 = dd * (f2 + s23.x);
    f3 = dd * (f3 + s23.y);

    if (lane < 13) {
        float4 fv = make_float4(f0, f1, f2, f3);
        *(float4*)&sAgg[wwid][lane * 4] = fv;
    }
    __syncwarp();
    if (lane < 20) {
        float ks = K8 * dd;
        int c = lane * 4;
        int t = c >> 4;
        int h = c & 15;
        float o0 = sB[h], o1 = sB[h + 1], o2 = sB[h + 2], o3 = sB[h + 3];
#pragma unroll
        for (int f = 0; f < FIN; f++) {
            float a = sAgg[wwid][t * FIN + f];
            o0 = fmaf(a, sW[f * 16 + h],     o0);
            o1 = fmaf(a, sW[f * 16 + h + 1], o1);
            o2 = fmaf(a, sW[f * 16 + h + 2], o2);
            o3 = fmaf(a, sW[f * 16 + h + 3], o3);
        }
        unsigned pk = pack_e4m3x4(ks * fmaxf(o0, 0.f), ks * fmaxf(o1, 0.f),
                                  ks * fmaxf(o2, 0.f), ks * fmaxf(o3, 0.f));
        ((unsigned*)(out + (size_t)node * F8STRIDE))[lane] = pk;
    }
}

// ---------------- stages 4/5: TRIPLE-row fp8 gather-sum --------------------------
// MODE 0 additionally resets cursor[node] to 0 (last reader) for the next replay.
template <int MODE>
__global__ __launch_bounds__(256, 8) void kprop8(const unsigned char* __restrict__ in,
                                                 void* __restrict__ outv,
                                                 int* __restrict__ cursor,
                                                 const int* __restrict__ csrc,
                                                 const float* __restrict__ dis,
                                                 const float* __restrict__ Wm,
                                                 const float* __restrict__ bm, int n) {
    __shared__ float sAgg[MODE ? 8 : 1][MODE ? 80 : 4];
    __shared__ float sW[MODE ? HID * 16 : 1];
    __shared__ float sB[MODE ? 16 : 1];
    if (MODE) {
        for (int i = threadIdx.x; i < HID * 16; i += blockDim.x) sW[i] = Wm[i];
        if (threadIdx.x < 16) sB[threadIdx.x] = bm[threadIdx.x];
        __syncthreads();
    }
    int wwid = threadIdx.x >> 5;
    int node = (blockIdx.x << 3) + wwid;
    if (node >= n) return;
    int lane = threadIdx.x & 31;
    int g = lane / 10; if (g > 2) g = 2;
    int lh = lane - g * 10; if (lh > 9) lh = 9;
    const unsigned FULL = 0xffffffffu;

    __half2 zero2 = __float2half2_rn(0.f);
    __half2 a0 = zero2, a1 = zero2, a2 = zero2, a3 = zero2;

    int base = node * CAP;
    int deg = __ldg(cursor + node);
    if (deg > CAP) deg = CAP;
    if (MODE == 0 && lane == 31) cursor[node] = 0;   // reset for next replay
    int end3 = base + ((deg + 2) / 3) * 3;           // padded region is valid

    int j = base;
    for (; j + 6 <= end3; j += 6) {
        int s0 = __ldg(csrc + j + g);
        int s1 = __ldg(csrc + j + 3 + g);
        uint2 q0 = __ldg((const uint2*)(in + (size_t)s0 * F8STRIDE) + lh);
        uint2 q1 = __ldg((const uint2*)(in + (size_t)s1 * F8STRIDE) + lh);
        __half2 pa, pb;
        unpack_e4m3x4(q0.x, pa, pb); a0 = __hadd2(a0, pa); a1 = __hadd2(a1, pb);
        unpack_e4m3x4(q0.y, pa, pb); a2 = __hadd2(a2, pa); a3 = __hadd2(a3, pb);
        unpack_e4m3x4(q1.x, pa, pb); a0 = __hadd2(a0, pa); a1 = __hadd2(a1, pb);
        unpack_e4m3x4(q1.y, pa, pb); a2 = __hadd2(a2, pa); a3 = __hadd2(a3, pb);
    }
    if (j < end3) {
        int s0 = __ldg(csrc + j + g);
        uint2 q0 = __ldg((const uint2*)(in + (size_t)s0 * F8STRIDE) + lh);
        __half2 pa, pb;
        unpack_e4m3x4(q0.x, pa, pb); a0 = __hadd2(a0, pa); a1 = __hadd2(a1, pb);
        unpack_e4m3x4(q0.y, pa, pb); a2 = __hadd2(a2, pa); a3 = __hadd2(a3, pb);
    }

    float v[8];
    float2 t2;
    t2 = __half22float2(a0); v[0] = t2.x; v[1] = t2.y;
    t2 = __half22float2(a1); v[2] = t2.x; v[3] = t2.y;
    t2 = __half22float2(a2); v[4] = t2.x; v[5] = t2.y;
    t2 = __half22float2(a3); v[6] = t2.x; v[7] = t2.y;
#pragma unroll
    for (int k = 0; k < 8; k++) {
        float b1v = __shfl_sync(FULL, v[k], lh + 10);
        float b2v = __shfl_sync(FULL, v[k], lh + 20);
        v[k] += b1v + b2v;
    }

    float dd = __ldg(dis + node);
    float sc = dd * (1.0f / K8);
    uint2 sq = __ldg((const uint2*)(in + (size_t)node * F8STRIDE) + lh);
    __half2 sa, sb;
    unpack_e4m3x4(sq.x, sa, sb);
    float2 s01 = __half22float2(sa), s23 = __half22float2(sb);
    v[0] = sc * (v[0] + s01.x); v[1] = sc * (v[1] + s01.y);
    v[2] = sc * (v[2] + s23.x); v[3] = sc * (v[3] + s23.y);
    unpack_e4m3x4(sq.y, sa, sb);
    s01 = __half22float2(sa); s23 = __half22float2(sb);
    v[4] = sc * (v[4] + s01.x); v[5] = sc * (v[5] + s01.y);
    v[6] = sc * (v[6] + s23.x); v[7] = sc * (v[7] + s23.y);

    if (!MODE) {
        if (lane < 10) {
            __half2 p0 = __floats2half2_rn(v[0], v[1]);
            __half2 p1 = __floats2half2_rn(v[2], v[3]);
            __half2 p2 = __floats2half2_rn(v[4], v[5]);
            __half2 p3 = __floats2half2_rn(v[6], v[7]);
            uint4 pk;
            pk.x = *reinterpret_cast<unsigned*>(&p0);
            pk.y = *reinterpret_cast<unsigned*>(&p1);
            pk.z = *reinterpret_cast<unsigned*>(&p2);
            pk.w = *reinterpret_cast<unsigned*>(&p3);
            *((uint4*)((__half*)outv + (size_t)node * FSTRIDE) + lh) = pk;
        }
        return;
    }

    if (lane < 10) {
        *(float4*)&sAgg[wwid][lh * 8]     = make_float4(v[0], v[1], v[2], v[3]);
        *(float4*)&sAgg[wwid][lh * 8 + 4] = make_float4(v[4], v[5], v[6], v[7]);
    }
    __syncwarp();
    if (lane < 20) {
        float ks = K8 * dd;
        int c = lane * 4;
        int t = c >> 4;
        int h = c & 15;
        float o0 = sB[h], o1 = sB[h + 1], o2 = sB[h + 2], o3 = sB[h + 3];
#pragma unroll
        for (int f = 0; f < HID; f++) {
            float a = sAgg[wwid][t * HID + f];
            o0 = fmaf(a, sW[f * 16 + h],     o0);
            o1 = fmaf(a, sW[f * 16 + h + 1], o1);
            o2 = fmaf(a, sW[f * 16 + h + 2], o2);
            o3 = fmaf(a, sW[f * 16 + h + 3], o3);
        }
        unsigned pk = pack_e4m3x4(ks * fmaxf(o0, 0.f), ks * fmaxf(o1, 0.f),
                                  ks * fmaxf(o2, 0.f), ks * fmaxf(o3, 0.f));
        ((unsigned*)((unsigned char*)outv + (size_t)node * F8STRIDE))[lane] = pk;
    }
}

// ---------------- GRU (FFMA2, half2-staged P — round-15 proven) ------------------
#define GRU_NPB 96
__global__ __launch_bounds__(GRU_NPB) void kgru(const __half* __restrict__ P,
                                                const float* __restrict__ Lz,
                                                const float* __restrict__ Lr,
                                                const float* __restrict__ Lh,
                                                const float* __restrict__ att,
                                                const float* __restrict__ fcW,
                                                const float* __restrict__ fcb,
                                                float* __restrict__ out, int n) {
    __shared__ unsigned long long sM2z[128], sM2r[128], sM2h[128];
    __shared__ unsigned long long sL2z[128], sL2r[128], sL2h[128];
    __shared__ unsigned long long sB2z[8], sB2r[8], sB2h[8];
    __shared__ unsigned sPh[GRU_NPB * 41];
    __shared__ float sfcW[32], sfcb[2], sprob[TT];

    int tid = threadIdx.x;
    for (int i = tid; i < 128; i += GRU_NPB) {
        int k = i >> 3, j = i & 7;
        int gi = k * 16 + 2 * j;
        sM2z[i] = pack2(g_Mz[gi], g_Mz[gi + 1]);
        sM2r[i] = pack2(g_Mr[gi], g_Mr[gi + 1]);
        sM2h[i] = pack2(g_Mh[gi], g_Mh[gi + 1]);
        sL2z[i] = pack2(Lz[256 + gi], Lz[256 + gi + 1]);
        sL2r[i] = pack2(Lr[256 + gi], Lr[256 + gi + 1]);
        sL2h[i] = pack2(Lh[256 + gi], Lh[256 + gi + 1]);
    }
    if (tid < 8) {
        sB2z[tid] = pack2(g_Bz[2 * tid], g_Bz[2 * tid + 1]);
        sB2r[tid] = pack2(g_Br[2 * tid], g_Br[2 * tid + 1]);
        sB2h[tid] = pack2(g_Bh[2 * tid], g_Bh[2 * tid + 1]);
    }
    if (tid < 32) sfcW[tid] = fcW[tid];
    if (tid < 2)  sfcb[tid] = fcb[tid];
    if (tid == 0) {
        float m = att[0];
        for (int t = 1; t < TT; t++) m = fmaxf(m, att[t]);
        float ex[TT]; float s = 0.f;
        for (int t = 0; t < TT; t++) { ex[t] = expf(att[t] - m); s += ex[t]; }
        for (int t = 0; t < TT; t++) sprob[t] = ex[t] / s;
    }
    int base = blockIdx.x * GRU_NPB;
    for (int i = tid; i < GRU_NPB * (FSTRIDE / 2); i += GRU_NPB) {
        int nd = i / (FSTRIDE / 2), c2 = i - nd * (FSTRIDE / 2);
        int g = base + nd;
        unsigned u = 0;
        if (g < n) u = __ldg((const unsigned*)(P + (size_t)g * FSTRIDE) + c2);
        sPh[nd * 41 + c2] = u;
    }
    __syncthreads();

    int node = base + tid;
    if (node >= n) return;
    const unsigned* myPh = &sPh[tid * 41];

    float H[16], Hacc[16];
#pragma unroll
    for (int h = 0; h < 16; h++) { H[h] = 0.f; Hacc[h] = 0.f; }

#pragma unroll 1
    for (int t = 0; t < TT; t++) {
        unsigned long long pk2[16], hk2[16];
#pragma unroll
        for (int k2 = 0; k2 < 8; k2++) {
            float2 pf = __half22float2(bits_h2u(myPh[t * 8 + k2]));
            pk2[2 * k2]     = pack2(pf.x, pf.x);
            pk2[2 * k2 + 1] = pack2(pf.y, pf.y);
        }
#pragma unroll
        for (int k = 0; k < 16; k++) hk2[k] = pack2(H[k], H[k]);

        unsigned long long acc[8];
        float a[16];
#pragma unroll
        for (int j = 0; j < 8; j++) acc[j] = sB2z[j];
#pragma unroll
        for (int k = 0; k < 16; k++) {
#pragma unroll
            for (int j = 0; j < 8; j++) {
                acc[j] = fma2(pk2[k], sM2z[k * 8 + j], acc[j]);
                acc[j] = fma2(hk2[k], sL2z[k * 8 + j], acc[j]);
            }
        }
        float Zg[16];
#pragma unroll
        for (int j = 0; j < 8; j++) unpack2(a[2 * j], a[2 * j + 1], acc[j]);
#pragma unroll
        for (int h = 0; h < 16; h++) Zg[h] = fast_sig(a[h]);

#pragma unroll
        for (int j = 0; j < 8; j++) acc[j] = sB2r[j];
#pragma unroll
        for (int k = 0; k < 16; k++) {
#pragma unroll
            for (int j = 0; j < 8; j++) {
                acc[j] = fma2(pk2[k], sM2r[k * 8 + j], acc[j]);
                acc[j] = fma2(hk2[k], sL2r[k * 8 + j], acc[j]);
            }
        }
        float Rg[16];
#pragma unroll
        for (int j = 0; j < 8; j++) unpack2(a[2 * j], a[2 * j + 1], acc[j]);
#pragma unroll
        for (int h = 0; h < 16; h++) Rg[h] = fast_sig(a[h]);

#pragma unroll
        for (int k = 0; k < 16; k++) {
            float hr = H[k] * Rg[k];
            hk2[k] = pack2(hr, hr);
        }
#pragma unroll
        for (int j = 0; j < 8; j++) acc[j] = sB2h[j];
#pragma unroll
        for (int k = 0; k < 16; k++) {
#pragma unroll
            for (int j = 0; j < 8; j++) {
                acc[j] = fma2(pk2[k], sM2h[k * 8 + j], acc[j]);
                acc[j] = fma2(hk2[k], sL2h[k * 8 + j], acc[j]);
            }
        }
#pragma unroll
        for (int j = 0; j < 8; j++) unpack2(a[2 * j], a[2 * j + 1], acc[j]);
#pragma unroll
        for (int h = 0; h < 16; h++) {
            float ht = fast_tanh(a[h]);
            H[h] = Zg[h] * H[h] + (1.f - Zg[h]) * ht;
            Hacc[h] = fmaf(sprob[t], H[h], Hacc[h]);
        }
    }

    float l0 = sfcb[0], l1 = sfcb[1];
#pragma unroll
    for (int h = 0; h < 16; h++) {
        l0 = fmaf(Hacc[h], sfcW[h * 2 + 0], l0);
        l1 = fmaf(Hacc[h], sfcW[h * 2 + 1], l1);
    }
    float m = fmaxf(l0, l1);
    float lse = m + logf(expf(l0 - m) + expf(l1 - m));
    out[(size_t)node * 2 + 0] = l0 - lse;
    out[(size_t)node * 2 + 1] = l1 - lse;
}

// ---------------- launch ----------------
extern "C" void kernel_launch(void* const* d_in, const int* in_sizes, int n_in,
                              void* d_out, int out_size) {
    const float* x   = (const float*)d_in[0];
    const int*   src = (const int*)d_in[1];
    const int*   dst = (const int*)d_in[2];
    const float* W1  = (const float*)d_in[3];
    const float* b1  = (const float*)d_in[4];
    const float* W2  = (const float*)d_in[5];
    const float* b2  = (const float*)d_in[6];
    const float* Wz  = (const float*)d_in[7];
    const float* bz  = (const float*)d_in[8];
    const float* Wr  = (const float*)d_in[9];
    const float* br  = (const float*)d_in[10];
    const float* Wh  = (const float*)d_in[11];
    const float* bh  = (const float*)d_in[12];
    const float* Lz  = (const float*)d_in[13];
    const float* lz  = (const float*)d_in[14];
    const float* Lr  = (const float*)d_in[15];
    const float* lr  = (const float*)d_in[16];
    const float* Lh  = (const float*)d_in[17];
    const float* lh  = (const float*)d_in[18];
    const float* att = (const float*)d_in[19];
    const float* fcW = (const float*)d_in[20];
    const float* fcb = (const float*)d_in[21];

    int n = in_sizes[0] / (TT * FIN);
    int e = in_sizes[1];

    void* p;
    cudaGetSymbolAddress(&p, g_cursor);  int*           cursor = (int*)p;
    cudaGetSymbolAddress(&p, g_dis);     float*         dis    = (float*)p;
    cudaGetSymbolAddress(&p, g_csrc);    int*           csrc   = (int*)p;
    cudaGetSymbolAddress(&p, g_xT);      __half*        xT     = (__half*)p;
    cudaGetSymbolAddress(&p, g_h1);      unsigned char* h1     = (unsigned char*)p;
    cudaGetSymbolAddress(&p, g_feats);   unsigned char* feats  = (unsigned char*)p;
    cudaGetSymbolAddress(&p, g_P);       __half*        P      = (__half*)p;

    int e8 = (e + 7) / 8;
    int prop_blocks = (n + 7) / 8;

    // 0: fold GRU gate weights (separate small kernel — round-15 proven)
    kprepG<<<1, 256>>>(Wz, bz, Wr, br, Wh, bh, Lz, lz, Lr, lr, Lh, lh);
    // 1: single-pass edge fill (zero-based cursors; no init kernel)
    kfill<<<(e8 + 255) / 256, 256>>>(src, dst, cursor, csrc, e);
    // 2: x transpose (pre-scaled) + dis + slice pad-to-3
    ktransd<<<(n * XREAL2 + 255) / 256, 256>>>(x, xT, cursor, dis, csrc, n);
    // 3: h1(fp8) = K8*dis*relu((S x) @ W1 + b1)   [dual-row]  <-- profiled
    kprop_x<<<prop_blocks, 256>>>(xT, h1, cursor, csrc, dis, W1, b1, n);
    // 4: feats(fp8) = K8*dis*relu((S h1) @ W2 + b2)   [triple-row]
    kprop8<1><<<prop_blocks, 256>>>(h1, feats, cursor, csrc, dis, W2, b2, n);
    // 5: P(fp16) = S feats [triple-row] + cursor reset for next replay
    kprop8<0><<<prop_blocks, 256>>>(feats, P, cursor, csrc, dis, W2, b2, n);
    // 6: GRU (FFMA2) + attention + FC + log_softmax
    kgru<<<(n + GRU_NPB - 1) / GRU_NPB, GRU_NPB>>>(P, Lz, Lr, Lh, att, fcW, fcb,
                                                   (float*)d_out, n);
}